// round 4
// baseline (speedup 1.0000x reference)
#include <cuda_runtime.h>
#include <float.h>
#include <math.h>

// SpectoCapsLayer: capsule routing
//   x: [B=256, I=1152, F=8] fp32
//   W: [I=1152, O=10, F=8, G=16] fp32
//   u[b,i,o,g] = sum_f x[b,i,f] * W[i,o,f,g]
//   3 routing steps; logits_t = u . (sum of previous v's)  (closed form)
//   out = [ v3: (B,O,G) 40960 floats | u: (B,I,O,G) 47185920 floats ]

#define TPB 512
#define B_DIM 256
#define I_DIM 1152
#define O_DIM 10
#define F_DIM 8
#define G_DIM 16
#define BTILE 2
#define PAIRS (BTILE * I_DIM)            // 2304
#define U_FLOATS (PAIRS * G_DIM)         // 36864 (147456 B)
#define REGB_FLOATS 4384                 // d_s(2304) + scratch(2048) + wred(32)
#define SMALL_FLOATS 128
#define SMEM_FLOATS (U_FLOATS + REGB_FLOATS + SMALL_FLOATS)
#define SMEM_BYTES (SMEM_FLOATS * 4)     // 165504 B

// small-region indices
#define SM_VSUM 0   // [2][16] running sum of v's
#define SM_M    64  // m0, m1 (softmax max per b)
#define SM_Z    66  // Z0, Z1 (softmax denom per b)

__device__ __forceinline__ void block_reduce2_max(float v0, float v1, float* wred,
                                                  float* small, int tid) {
    const unsigned FULL = 0xffffffffu;
    #pragma unroll
    for (int off = 16; off > 0; off >>= 1) {
        v0 = fmaxf(v0, __shfl_xor_sync(FULL, v0, off));
        v1 = fmaxf(v1, __shfl_xor_sync(FULL, v1, off));
    }
    int lane = tid & 31, wid = tid >> 5;
    if (lane == 0) { wred[wid * 2] = v0; wred[wid * 2 + 1] = v1; }
    __syncthreads();
    if (tid == 0) {
        float a0 = wred[0], a1 = wred[1];
        #pragma unroll
        for (int w = 1; w < TPB / 32; w++) {
            a0 = fmaxf(a0, wred[w * 2]);
            a1 = fmaxf(a1, wred[w * 2 + 1]);
        }
        small[SM_M] = a0; small[SM_M + 1] = a1;
    }
    __syncthreads();
}

__device__ __forceinline__ void block_reduce2_sum(float v0, float v1, float* wred,
                                                  float* small, int tid) {
    const unsigned FULL = 0xffffffffu;
    #pragma unroll
    for (int off = 16; off > 0; off >>= 1) {
        v0 += __shfl_xor_sync(FULL, v0, off);
        v1 += __shfl_xor_sync(FULL, v1, off);
    }
    int lane = tid & 31, wid = tid >> 5;
    if (lane == 0) { wred[wid * 2] = v0; wred[wid * 2 + 1] = v1; }
    __syncthreads();
    if (tid == 0) {
        float a0 = wred[0], a1 = wred[1];
        #pragma unroll
        for (int w = 1; w < TPB / 32; w++) {
            a0 += wred[w * 2];
            a1 += wred[w * 2 + 1];
        }
        small[SM_Z] = a0; small[SM_Z + 1] = a1;
    }
    __syncthreads();
}

// Reduce 128-group partials -> s[2][16], divide by Z, squash, accumulate into Vsum.
// Optionally write v to gmem (final step).
__device__ __forceinline__ void finish_step(float* scratch, float* small, int tid,
                                            float invZ0, float invZ1,
                                            bool write_out, float* out_v,
                                            int b_base, int o) {
    if (tid < 32) {
        int b = tid >> 4, g = tid & 15;
        float s = 0.f;
        const float* sc = scratch + (b * 64) * 16 + g;
        #pragma unroll 8
        for (int grp = 0; grp < 64; grp++) s += sc[grp * 16];
        s *= (b ? invZ1 : invZ0);
        // squash: v = s * n / (n^2 + 1), n = ||s|| over g (16 lanes)
        float sq = s * s;
        #pragma unroll
        for (int off = 8; off > 0; off >>= 1)
            sq += __shfl_xor_sync(0xffffffffu, sq, off);   // stays within 16-lane half
        float n = sqrtf(sq);
        float fac = n / (sq + 1.0f);
        float v = s * fac;
        small[SM_VSUM + tid] += v;
        if (write_out)
            out_v[((b_base + b) * O_DIM + o) * G_DIM + g] = v;
    }
    __syncthreads();
}

__global__ void __launch_bounds__(TPB, 1)
caps_kernel(const float* __restrict__ x, const float* __restrict__ W,
            float* __restrict__ out_v, float* __restrict__ out_u) {
    extern __shared__ float sm[];
    float* u_s     = sm;                        // 36864 floats
    float* d_s     = sm + U_FLOATS;             // 2304 floats
    float* scratch = sm + U_FLOATS + 2304;      // 2048 floats
    float* wred    = sm + U_FLOATS + 4352;      // 32 floats
    float* small   = sm + U_FLOATS + REGB_FLOATS; // 128 floats

    const int tid = threadIdx.x;
    const int o = blockIdx.y;
    const int b_base = blockIdx.x * BTILE;

    if (tid < 32) small[SM_VSUM + tid] = 0.f;
    __syncthreads();

    // ---- phase 1: compute u, write to smem + gmem, accumulate uniform-weight sum ----
    const int group = tid >> 2;          // 0..127; 128 groups of 4 threads
    const int q = tid & 3;               // float4 (4 g's) within the 16 g's
    const int bloc = group >> 6;         // groups 0..63 -> b=0, 64..127 -> b=1
    const int i0 = (group & 63) * 18;    // 64 groups * 18 = 1152 i's per b

    {
        float a0 = 0.f, a1 = 0.f, a2 = 0.f, a3 = 0.f;
        const float4* Wv = reinterpret_cast<const float4*>(W);
        const float4* xv = reinterpret_cast<const float4*>(
            x + ((size_t)(b_base + bloc) * I_DIM + i0) * F_DIM);
        #pragma unroll 2
        for (int k = 0; k < 18; k++) {
            int i = i0 + k;
            int p = bloc * I_DIM + i;
            const float4* wb = Wv + (((size_t)(i * O_DIM + o)) << 5) + q;
            // x row: 8 floats, broadcast-read by the 4 threads of this group
            float4 x0 = xv[k * 2];
            float4 x1 = xv[k * 2 + 1];
            float xf[8] = {x0.x, x0.y, x0.z, x0.w, x1.x, x1.y, x1.z, x1.w};
            float4 r = make_float4(0.f, 0.f, 0.f, 0.f);
            #pragma unroll
            for (int f = 0; f < F_DIM; f++) {
                float4 w = wb[f * 4];
                float xvv = xf[f];
                r.x = fmaf(xvv, w.x, r.x);
                r.y = fmaf(xvv, w.y, r.y);
                r.z = fmaf(xvv, w.z, r.z);
                r.w = fmaf(xvv, w.w, r.w);
            }
            reinterpret_cast<float4*>(u_s + p * G_DIM)[q] = r;
            size_t go = (((size_t)(b_base + bloc) * I_DIM + i) * O_DIM + o) << 4;
            reinterpret_cast<float4*>(out_u + go)[q] = r;
            a0 += r.x; a1 += r.y; a2 += r.z; a3 += r.w;
        }
        float* scr = scratch + group * 16 + q * 4;
        scr[0] = a0; scr[1] = a1; scr[2] = a2; scr[3] = a3;
        __syncthreads();
    }

    // step 1: uniform coefficients -> mean over i
    finish_step(scratch, small, tid, 1.0f / I_DIM, 1.0f / I_DIM,
                false, out_v, b_base, o);

    // ---- routing steps 2 and 3 ----
    #pragma unroll 1
    for (int step = 1; step < 3; step++) {
        // Pass A: d[p] = u[p] . Vsum[b], running max per b
        float pm0 = -FLT_MAX, pm1 = -FLT_MAX;
        #pragma unroll
        for (int k = 0; k < 5; k++) {
            int p = tid + k * TPB;
            if (p < PAIRS) {
                int b = (p >= I_DIM);
                const float4* up = reinterpret_cast<const float4*>(u_s + p * G_DIM);
                const float4* Vp = reinterpret_cast<const float4*>(small + SM_VSUM + b * G_DIM);
                float dot = 0.f;
                #pragma unroll
                for (int j = 0; j < 4; j++) {
                    float4 u4 = up[j]; float4 v4 = Vp[j];
                    dot = fmaf(u4.x, v4.x, dot);
                    dot = fmaf(u4.y, v4.y, dot);
                    dot = fmaf(u4.z, v4.z, dot);
                    dot = fmaf(u4.w, v4.w, dot);
                }
                d_s[p] = dot;
                if (b) pm1 = fmaxf(pm1, dot); else pm0 = fmaxf(pm0, dot);
            }
        }
        block_reduce2_max(pm0, pm1, wred, small, tid);
        float m0 = small[SM_M], m1 = small[SM_M + 1];

        // Pass B: exponentiate in place, running sum per b
        float pz0 = 0.f, pz1 = 0.f;
        #pragma unroll
        for (int k = 0; k < 5; k++) {
            int p = tid + k * TPB;
            if (p < PAIRS) {
                int b = (p >= I_DIM);
                float e = __expf(d_s[p] - (b ? m1 : m0));
                d_s[p] = e;
                if (b) pz1 += e; else pz0 += e;
            }
        }
        block_reduce2_sum(pz0, pz1, wred, small, tid);
        float invZ0 = 1.0f / small[SM_Z];
        float invZ1 = 1.0f / small[SM_Z + 1];

        // Pass C: weighted accumulation (group mapping, same as phase 1)
        float a0 = 0.f, a1 = 0.f, a2 = 0.f, a3 = 0.f;
        #pragma unroll 2
        for (int k = 0; k < 18; k++) {
            int p = bloc * I_DIM + i0 + k;
            float e = d_s[p];
            float4 u4 = reinterpret_cast<const float4*>(u_s + p * G_DIM)[q];
            a0 = fmaf(e, u4.x, a0);
            a1 = fmaf(e, u4.y, a1);
            a2 = fmaf(e, u4.z, a2);
            a3 = fmaf(e, u4.w, a3);
        }
        __syncthreads();   // all d_s reads done before scratch overwrite
        float* scr = scratch + group * 16 + q * 4;
        scr[0] = a0; scr[1] = a1; scr[2] = a2; scr[3] = a3;
        __syncthreads();

        finish_step(scratch, small, tid, invZ0, invZ1,
                    (step == 2), out_v, b_base, o);
    }
}

extern "C" void kernel_launch(void* const* d_in, const int* in_sizes, int n_in,
                              void* d_out, int out_size) {
    const float* x = (const float*)d_in[0];   // [256,1152,8]
    const float* W = (const float*)d_in[1];   // [1152,10,8,16]
    float* out = (float*)d_out;
    float* out_v = out;                         // [256,10,16] = 40960
    float* out_u = out + B_DIM * O_DIM * G_DIM; // [256,1152,10,16]

    cudaFuncSetAttribute(caps_kernel,
                         cudaFuncAttributeMaxDynamicSharedMemorySize, SMEM_BYTES);
    dim3 grid(B_DIM / BTILE, O_DIM);
    caps_kernel<<<grid, TPB, SMEM_BYTES>>>(x, W, out_v, out_u);
}

// round 7
// speedup vs baseline: 1.4952x; 1.4952x over previous
#include <cuda_runtime.h>
#include <float.h>
#include <math.h>

// SpectoCapsLayer: capsule routing, register-resident u.
//   x: [B=256, I=1152, F=8] fp32
//   W: [I=1152, O=10, F=8, G=16] fp32
//   u[b,i,o,g] = sum_f x[b,i,f] * W[i,o,f,g]
//   3 routing steps; logits_t = u . (sum of previous v's)  (closed form)
//   out = [ v3: (B,O,G) 40960 floats | u: (B,I,O,G) 47185920 floats ]
//
// Mapping: 512 threads = 128 quads. Quad owns 18 i's; thread q in quad owns
// g-slice [4q, 4q+4). u stays in registers (18 float4/thread). Routing dots
// are completed with 2 quad shuffles; softmax uses no max-subtraction
// (dot magnitude bounded ~25, exp safe in fp32).

#define TPB 512
#define B_DIM 256
#define I_DIM 1152
#define O_DIM 10
#define F_DIM 8
#define G_DIM 16
#define BTILE 2
#define IPT 18                            // i's per quad

// static shared: scratch(2048) + wred(32) + small(128)
#define SCRATCH_OFF 0
#define WRED_OFF    2048
#define SMALL_OFF   2080
#define SM_TOTAL    2208

// small-region indices
#define SM_VSUM 0   // [2][16] running sum of v's
#define SM_Z    64  // Z0, Z1

__device__ __forceinline__ void block_reduce2_sum(float v0, float v1, float* wred,
                                                  float* small, int tid) {
    const unsigned FULL = 0xffffffffu;
    #pragma unroll
    for (int off = 16; off > 0; off >>= 1) {
        v0 += __shfl_xor_sync(FULL, v0, off);
        v1 += __shfl_xor_sync(FULL, v1, off);
    }
    int lane = tid & 31, wid = tid >> 5;
    if (lane == 0) { wred[wid * 2] = v0; wred[wid * 2 + 1] = v1; }
    __syncthreads();
    if (tid == 0) {
        float a0 = wred[0], a1 = wred[1];
        #pragma unroll
        for (int w = 1; w < TPB / 32; w++) {
            a0 += wred[w * 2];
            a1 += wred[w * 2 + 1];
        }
        small[SM_Z] = a0; small[SM_Z + 1] = a1;
    }
    __syncthreads();
}

// Reduce 128-group partials -> s[2][16], scale by invZ, squash, accumulate Vsum.
__device__ __forceinline__ void finish_step(float* scratch, float* small, int tid,
                                            float invZ0, float invZ1,
                                            bool write_out, float* out_v,
                                            int b_base, int o) {
    if (tid < 32) {
        int b = tid >> 4, g = tid & 15;
        float s = 0.f;
        const float* sc = scratch + (b * 64) * 16 + g;
        #pragma unroll 8
        for (int grp = 0; grp < 64; grp++) s += sc[grp * 16];
        s *= (b ? invZ1 : invZ0);
        // squash: v = s * n / (n^2 + 1), n = ||s|| over g (16 lanes)
        float sq = s * s;
        #pragma unroll
        for (int off = 8; off > 0; off >>= 1)
            sq += __shfl_xor_sync(0xffffffffu, sq, off);   // stays in 16-lane half
        float n = sqrtf(sq);
        float fac = n / (sq + 1.0f);
        float v = s * fac;
        small[SM_VSUM + tid] += v;
        if (write_out)
            out_v[((b_base + b) * O_DIM + o) * G_DIM + g] = v;
    }
    __syncthreads();
}

__global__ void __launch_bounds__(TPB, 1)
caps_kernel(const float* __restrict__ x, const float* __restrict__ W,
            float* __restrict__ out_v, float* __restrict__ out_u) {
    __shared__ float sm[SM_TOTAL];
    float* scratch = sm + SCRATCH_OFF;   // 2048 floats (128 groups x 16)
    float* wred    = sm + WRED_OFF;      // 32 floats
    float* small   = sm + SMALL_OFF;     // 128 floats

    const int tid = threadIdx.x;
    const int o = blockIdx.y;
    const int b_base = blockIdx.x * BTILE;

    const int group = tid >> 2;          // 0..127
    const int q = tid & 3;               // g-slice [4q,4q+4)
    const int bloc = group >> 6;         // 0 or 1
    const int i0 = (group & 63) * IPT;   // 64 quads x 18 = 1152 i per b

    if (tid < 32) small[SM_VSUM + tid] = 0.f;
    __syncthreads();

    // ---- phase 1: compute u into registers, store to gmem, uniform-weight sums ----
    float4 u[IPT];
    {
        float a0 = 0.f, a1 = 0.f, a2 = 0.f, a3 = 0.f;
        const float4* Wv = reinterpret_cast<const float4*>(W);
        const float4* xv = reinterpret_cast<const float4*>(
            x + ((size_t)(b_base + bloc) * I_DIM + i0) * F_DIM);
        float4* out_base = reinterpret_cast<float4*>(
            out_u + ((((size_t)(b_base + bloc) * I_DIM + i0) * O_DIM + o) << 4)) + q;
        #pragma unroll
        for (int k = 0; k < IPT; k++) {
            int i = i0 + k;
            const float4* wb = Wv + ((size_t)(i * O_DIM + o) << 5) + q;
            float4 x0 = xv[k * 2];
            float4 x1 = xv[k * 2 + 1];
            float xf[8] = {x0.x, x0.y, x0.z, x0.w, x1.x, x1.y, x1.z, x1.w};
            float4 r = make_float4(0.f, 0.f, 0.f, 0.f);
            #pragma unroll
            for (int f = 0; f < F_DIM; f++) {
                float4 w = wb[f * 4];
                float xvv = xf[f];
                r.x = fmaf(xvv, w.x, r.x);
                r.y = fmaf(xvv, w.y, r.y);
                r.z = fmaf(xvv, w.z, r.z);
                r.w = fmaf(xvv, w.w, r.w);
            }
            u[k] = r;
            out_base[(size_t)k * O_DIM * 4] = r;   // stride O*16 floats = O*4 float4
            a0 += r.x; a1 += r.y; a2 += r.z; a3 += r.w;
        }
        float* scr = scratch + group * 16 + q * 4;
        scr[0] = a0; scr[1] = a1; scr[2] = a2; scr[3] = a3;
        __syncthreads();
    }

    // step 1: uniform coefficients -> mean over i
    finish_step(scratch, small, tid, 1.0f / I_DIM, 1.0f / I_DIM,
                false, out_v, b_base, o);

    // ---- routing steps 2 and 3 (all register-resident) ----
    const unsigned FULL = 0xffffffffu;
    #pragma unroll 1
    for (int step = 1; step < 3; step++) {
        // per-i dot with Vsum (quad-completed), exp, partial Z
        float4 V = reinterpret_cast<const float4*>(small + SM_VSUM + bloc * G_DIM)[q];
        float e[IPT];
        float pz = 0.f;
        #pragma unroll
        for (int k = 0; k < IPT; k++) {
            float d = u[k].x * V.x + u[k].y * V.y + u[k].z * V.z + u[k].w * V.w;
            d += __shfl_xor_sync(FULL, d, 1);
            d += __shfl_xor_sync(FULL, d, 2);     // full 16-g dot, all quad lanes
            float ev = __expf(d);                 // bounded: |d| <~ 25, safe in fp32
            e[k] = ev;
            pz += ev;
        }
        // Z per b (quad-replicated x4)
        block_reduce2_sum(bloc ? 0.f : pz, bloc ? pz : 0.f, wred, small, tid);
        float invZ0 = 4.0f / small[SM_Z];
        float invZ1 = 4.0f / small[SM_Z + 1];

        // weighted accumulation from registers
        float a0 = 0.f, a1 = 0.f, a2 = 0.f, a3 = 0.f;
        #pragma unroll
        for (int k = 0; k < IPT; k++) {
            float ev = e[k];
            a0 = fmaf(ev, u[k].x, a0);
            a1 = fmaf(ev, u[k].y, a1);
            a2 = fmaf(ev, u[k].z, a2);
            a3 = fmaf(ev, u[k].w, a3);
        }
        float* scr = scratch + group * 16 + q * 4;
        scr[0] = a0; scr[1] = a1; scr[2] = a2; scr[3] = a3;
        __syncthreads();

        finish_step(scratch, small, tid, invZ0, invZ1,
                    (step == 2), out_v, b_base, o);
    }
}

extern "C" void kernel_launch(void* const* d_in, const int* in_sizes, int n_in,
                              void* d_out, int out_size) {
    const float* x = (const float*)d_in[0];   // [256,1152,8]
    const float* W = (const float*)d_in[1];   // [1152,10,8,16]
    float* out = (float*)d_out;
    float* out_v = out;                         // [256,10,16] = 40960
    float* out_u = out + B_DIM * O_DIM * G_DIM; // [256,1152,10,16]

    dim3 grid(B_DIM / BTILE, O_DIM);
    caps_kernel<<<grid, TPB>>>(x, W, out_v, out_u);
}